// round 1
// baseline (speedup 1.0000x reference)
#include <cuda_runtime.h>
#include <cuda_bf16.h>

// Problem constants (fixed by the reference)
static constexpr int BN = 262144;   // batch
static constexpr int KN = 3;        // centers per class
static constexpr int DN = 64;       // feature dim
static constexpr float TH_F  = 0.95f;
static constexpr float EPS_F = 1e-12f;

// Global accumulators (doubles for order-insensitive precision)
__device__ double g_sum_min;
__device__ double g_sum_masked;
__device__ double g_cnt;

__global__ void zero_accum_kernel() {
    g_sum_min = 0.0;
    g_sum_masked = 0.0;
    g_cnt = 0.0;
}

// Each warp handles 2 rows per iteration.
// lane = h*16 + sub : half h owns row (pair*2 + h), lane loads float4 #sub of that row.
// Warp-wide x load = 32 consecutive float4 = 512 contiguous bytes (fully coalesced).
__global__ void __launch_bounds__(256, 8)
dist_kernel(const float4* __restrict__ x4,
            const int*    __restrict__ labels,
            const float4* __restrict__ c4)
{
    const int lane    = threadIdx.x & 31;
    const int sub     = lane & 15;
    const int h       = lane >> 4;
    const int warp_id = (blockIdx.x * blockDim.x + threadIdx.x) >> 5;
    const int nwarps  = (gridDim.x * blockDim.x) >> 5;

    float acc_min = 0.f, acc_msk = 0.f, acc_cnt = 0.f;

    #pragma unroll 2
    for (int pair = warp_id; pair < BN / 2; pair += nwarps) {
        const int row = pair * 2 + h;

        // x: 512B contiguous per warp
        const float4 xv = x4[pair * 32 + lane];

        // label: 16 lanes hit the same address -> single sector per half
        const int lab = __ldg(&labels[row]);
        const float4* cb = c4 + (size_t)lab * (KN * (DN / 4));

        // 3 partial squared distances over this lane's 4 elements
        float p0, p1, p2;
        {
            float4 cv = __ldg(&cb[0 * (DN / 4) + sub]);
            float d0 = xv.x - cv.x, d1 = xv.y - cv.y;
            float d2 = xv.z - cv.z, d3 = xv.w - cv.w;
            p0 = d0 * d0 + d1 * d1 + d2 * d2 + d3 * d3;
        }
        {
            float4 cv = __ldg(&cb[1 * (DN / 4) + sub]);
            float d0 = xv.x - cv.x, d1 = xv.y - cv.y;
            float d2 = xv.z - cv.z, d3 = xv.w - cv.w;
            p1 = d0 * d0 + d1 * d1 + d2 * d2 + d3 * d3;
        }
        {
            float4 cv = __ldg(&cb[2 * (DN / 4) + sub]);
            float d0 = xv.x - cv.x, d1 = xv.y - cv.y;
            float d2 = xv.z - cv.z, d3 = xv.w - cv.w;
            p2 = d0 * d0 + d1 * d1 + d2 * d2 + d3 * d3;
        }

        // Reduce within the 16-lane half (xor offsets < 16 never cross halves)
        #pragma unroll
        for (int o = 1; o < 16; o <<= 1) {
            p0 += __shfl_xor_sync(0xffffffffu, p0, o);
            p1 += __shfl_xor_sync(0xffffffffu, p1, o);
            p2 += __shfl_xor_sync(0xffffffffu, p2, o);
        }

        if (sub == 0) {
            // two smallest of three + min
            const float mn  = fminf(fminf(p0, p1), p2);
            const float mx  = fmaxf(fmaxf(p0, p1), p2);
            const float mid = (p0 + p1 + p2) - mn - mx;

            const float a = mn  + EPS_F;
            const float b = mid + EPS_F;
            const float p = a / (a + b);                  // p <= 0.5, p > 0
            const float ent = -(p * log2f(p) + (1.f - p) * log2f(1.f - p));

            acc_min += mn;
            if (ent <= TH_F) { acc_msk += mn; acc_cnt += 1.f; }
        }
    }

    // Warp reduce
    #pragma unroll
    for (int o = 16; o > 0; o >>= 1) {
        acc_min += __shfl_xor_sync(0xffffffffu, acc_min, o);
        acc_msk += __shfl_xor_sync(0xffffffffu, acc_msk, o);
        acc_cnt += __shfl_xor_sync(0xffffffffu, acc_cnt, o);
    }

    // Block reduce + one double atomic triple per block
    __shared__ float sm[3][8];
    const int wib = threadIdx.x >> 5;
    if (lane == 0) { sm[0][wib] = acc_min; sm[1][wib] = acc_msk; sm[2][wib] = acc_cnt; }
    __syncthreads();
    if (threadIdx.x == 0) {
        float a = 0.f, b = 0.f, c = 0.f;
        #pragma unroll
        for (int i = 0; i < 8; i++) { a += sm[0][i]; b += sm[1][i]; c += sm[2][i]; }
        atomicAdd(&g_sum_min,    (double)a);
        atomicAdd(&g_sum_masked, (double)b);
        atomicAdd(&g_cnt,        (double)c);
    }
}

__global__ void finalize_kernel(float* __restrict__ out) {
    out[0] = (float)(g_sum_min / (double)BN);
    out[1] = (float)(g_sum_masked / g_cnt);
}

extern "C" void kernel_launch(void* const* d_in, const int* in_sizes, int n_in,
                              void* d_out, int out_size) {
    const float* x       = (const float*)d_in[0];   // [B, D] f32
    const int*   labels  = (const int*)  d_in[1];   // [B] i32
    const float* centers = (const float*)d_in[2];   // [C, K, D] f32

    zero_accum_kernel<<<1, 1>>>();
    // 2048 blocks x 256 threads = 16384 warps -> 8 row-pairs per warp (grid-stride)
    dist_kernel<<<2048, 256>>>((const float4*)x, labels, (const float4*)centers);
    finalize_kernel<<<1, 1>>>((float*)d_out);
}